// round 16
// baseline (speedup 1.0000x reference)
#include <cuda_runtime.h>
#include <cuda_fp16.h>
#include <cstdint>

#define TSEQ 2048
#define HEADS 16

// ---- global scratch: fp16 K/V tile images + split-K partials ----
#define REG8MB 8388608
#define SCR_K 0
#define SCR_V REG8MB
__device__ __align__(16) unsigned char g_scratch[2 * REG8MB];
__device__ __align__(16) float g_po[64 * 2 * 128 * 64];   // [pair][part][row][64]
__device__ __align__(16) float g_pl[64 * 2 * 128];        // [pair][part][row]

// smem: 3-stage ring of {K,V} tiles
#define BUFSZ 16384
#define OKH 0
#define OVH 8192
#define SMTOT (3 * BUFSZ)   // 49152

#define SW(o) ((o) ^ (((o) >> 3) & 0x70))

#define QSCALE 0.18033688011112042f    // 0.125 * log2(e)
#define EBIAS  11.541560327111708f     // 8 * log2(e)
#define HONES  0x3C003C00u             // fp16x2 {1.0, 1.0}

__device__ __forceinline__ uint32_t smem_u32(const void* p) {
    uint32_t a;
    asm("{ .reg .u64 t; cvta.to.shared.u64 t, %1; cvt.u32.u64 %0, t; }" : "=r"(a) : "l"(p));
    return a;
}
#define CPA16(sa, g) asm volatile("cp.async.cg.shared.global [%0], [%1], 16;" :: "r"(sa), "l"(g))
#define CPCOMMIT()   asm volatile("cp.async.commit_group;" ::: "memory")
#define CPWAIT0()    asm volatile("cp.async.wait_group 0;" ::: "memory")
#define CPWAIT1()    asm volatile("cp.async.wait_group 1;" ::: "memory")

__device__ __forceinline__ void ldsm4(uint32_t addr, uint32_t r[4]) {
    asm volatile("ldmatrix.sync.aligned.m8n8.x4.shared.b16 {%0,%1,%2,%3}, [%4];"
        : "=r"(r[0]), "=r"(r[1]), "=r"(r[2]), "=r"(r[3]) : "r"(addr));
}
__device__ __forceinline__ void ldsm4t(uint32_t addr, uint32_t r[4]) {
    asm volatile("ldmatrix.sync.aligned.m8n8.x4.trans.shared.b16 {%0,%1,%2,%3}, [%4];"
        : "=r"(r[0]), "=r"(r[1]), "=r"(r[2]), "=r"(r[3]) : "r"(addr));
}
__device__ __forceinline__ void mma_f16(float c[4], const uint32_t a[4], uint32_t b0, uint32_t b1) {
    asm volatile("mma.sync.aligned.m16n8k16.row.col.f32.f16.f16.f32 "
        "{%0,%1,%2,%3}, {%4,%5,%6,%7}, {%8,%9}, {%0,%1,%2,%3};"
        : "+f"(c[0]), "+f"(c[1]), "+f"(c[2]), "+f"(c[3])
        : "r"(a[0]), "r"(a[1]), "r"(a[2]), "r"(a[3]), "r"(b0), "r"(b1));
}
__device__ __forceinline__ uint32_t pkh(float a, float b) {
    __half2 h = __floats2half2_rn(a, b);
    return *(uint32_t*)&h;
}
__device__ __forceinline__ float ex2f(float x) {
    float y; asm("ex2.approx.f32 %0, %1;" : "=f"(y) : "f"(x)); return y;
}

// ---------------- pre-pass: fp32 -> fp16 K/V tile images (2 x 16B out per thread) ----------------
__global__ void __launch_bounds__(256)
prep_kernel(const float* __restrict__ K, const float* __restrict__ V)
{
    const int t = blockIdx.x * 256 + threadIdx.x;     // 32-byte output index
    const int which = blockIdx.y;                     // 0=K 1=V
    const int bh  = t >> 13;                          // 8192 groups per (b,h)
    const int rem = t & 8191;
    const int row = rem >> 2, d16 = rem & 3;          // 4 threads per 64-elem row

    const float* src = (which == 0 ? K : V) + ((size_t)bh << 17) + row * 64 + d16 * 16;
    // 4 independent LDG.128
    float4 a0 = *(const float4*)(src);
    float4 a1 = *(const float4*)(src + 4);
    float4 b0 = *(const float4*)(src + 8);
    float4 b1 = *(const float4*)(src + 12);
    uint4 h0, h1;
    h0.x = pkh(a0.x, a0.y); h0.y = pkh(a0.z, a0.w);
    h0.z = pkh(a1.x, a1.y); h0.w = pkh(a1.z, a1.w);
    h1.x = pkh(b0.x, b0.y); h1.y = pkh(b0.z, b0.w);
    h1.z = pkh(b1.x, b1.y); h1.w = pkh(b1.z, b1.w);

    const size_t base = (which == 0) ? SCR_K : SCR_V;
    const uint32_t tilebase = ((uint32_t)bh << 18) + (uint32_t)((row >> 6) << 13);
    const uint32_t r7 = (uint32_t)((row & 63) << 7);
    const uint32_t off0 = tilebase + SW(r7 + ((uint32_t)(2 * d16)     << 4));
    const uint32_t off1 = tilebase + SW(r7 + ((uint32_t)(2 * d16 + 1) << 4));
    *(uint4*)(g_scratch + base + off0) = h0;
    *(uint4*)(g_scratch + base + off1) = h1;
}

// ---------------- combine pass for split-K pairs ----------------
__global__ void __launch_bounds__(256)
combine_kernel(float* __restrict__ O)
{
    const int gid = blockIdx.x * 256 + threadIdx.x;   // 131072 float4s
    const int p   = gid >> 11;
    const int rem = gid & 2047;
    const int row = rem >> 4;

    const float4 va = ((const float4*)g_po)[(p * 2 + 0) * 2048 + rem];
    const float4 vb = ((const float4*)g_po)[(p * 2 + 1) * 2048 + rem];
    const float inv = 1.0f / (g_pl[(p * 2 + 0) * 128 + row] + g_pl[(p * 2 + 1) * 128 + row]);
    float4 o = make_float4((va.x + vb.x) * inv, (va.y + vb.y) * inv,
                           (va.z + vb.z) * inv, (va.w + vb.w) * inv);

    const int qt = 8 + (p & 7), h = 12 + ((p >> 3) & 3), b = p >> 5;
    const int bh = b * HEADS + h;
    float* dst = O + (size_t)bh * TSEQ * 64 + (size_t)(qt * 128) * 64 + rem * 4;
    *(float4*)dst = o;
}

// ---------------- main kernel ----------------
__device__ __forceinline__ void issue_tile(uint32_t dst, const unsigned char* gk,
                                           const unsigned char* gv, int tid) {
    const uint32_t o = (uint32_t)tid * 32;
    CPA16(dst + OKH + o,      gk + o);
    CPA16(dst + OKH + o + 16, gk + o + 16);
    CPA16(dst + OVH + o,      gv + o);
    CPA16(dst + OVH + o + 16, gv + o + 16);
}

__global__ void __launch_bounds__(256, 2)
dswa_mma_kernel(const float* __restrict__ Q, const int* __restrict__ WS,
                float* __restrict__ O)
{
    extern __shared__ char sm[];
    const uint32_t sb = smem_u32(sm);
    const int tid  = threadIdx.x;
    const int lane = tid & 31;
    const int warp = tid >> 5;

    // ---- work decode: first 64 CTAs are split part-B halves (longest first) ----
    int b, h, qt, part = 0, pid = 0;
    bool split = false;
    {
        const int idx = blockIdx.x;
        if (idx < 64) {
            pid = idx; part = 1; split = true;
            qt = 8 + (pid & 7); h = 12 + ((pid >> 3) & 3); b = pid >> 5;
        } else {
            const int e = idx - 64;
            qt = 15 - (e & 15); h = 15 - ((e >> 4) & 15); b = e >> 8;
            if (h >= 12 && qt >= 8) {
                split = true; part = 0;
                pid = (b << 5) | ((h - 12) << 3) | (qt - 8);
            }
        }
    }
    const int qbase = qt * 128;
    const int bh = b * HEADS + h;

    const unsigned uw = (unsigned)WS[h];
    float* Og = O + (size_t)bh * TSEQ * 64;

    const size_t bhoff = (size_t)bh << 18;
    const unsigned char* gK = g_scratch + SCR_K + bhoff;
    const unsigned char* gV = g_scratch + SCR_V + bhoff;

    int klo = qbase - (int)uw; if (klo < 0) klo = 0;
    int kt0 = klo >> 6;
    int kt1 = (qbase + 127) >> 6;
    if (split) { if (part == 0) kt1 = qt; else kt0 = qt + 1; }   // full-window: klo=0
    const int nkt = kt1 - kt0;

    // ---- prologue: first two K/V tiles via cp.async (3-stage ring) ----
    issue_tile(sb, gK + ((size_t)kt0 << 13), gV + ((size_t)kt0 << 13), tid);
    CPCOMMIT();
    if (nkt >= 1) {
        issue_tile(sb + BUFSZ, gK + ((size_t)(kt0 + 1) << 13), gV + ((size_t)(kt0 + 1) << 13), tid);
        CPCOMMIT();
    }

    // ---- lane mapping ----
    const int l7 = lane & 7, jm = lane >> 3;
    const uint32_t krowb = (uint32_t)((l7 + ((jm & 2) << 2)) * 128 + ((jm & 1) << 4));
    const uint32_t vrowb = (uint32_t)((l7 + ((jm & 1) << 3)) * 128 + ((jm & 2) << 3));
    uint32_t swK[4], swV[4];
    #pragma unroll
    for (int ks = 0; ks < 4; ks++) {
        swK[ks] = SW(krowb + (uint32_t)(ks * 32));
        swV[ks] = SW(vrowb + (uint32_t)(ks * 32));   // indexed by dp below
    }

    const int g  = lane >> 2;
    const int t4 = lane & 3;
    const int r0  = qbase + warp * 16;
    const int rq0 = r0 + g;

    // ---- Q fragments: direct fp32 global load -> fp16 fragments (once) ----
    uint32_t qfr[4][4];
    {
        const float* q0 = Q + (size_t)bh * TSEQ * 64 + (size_t)(r0 + g) * 64 + 2 * t4;
        const float* q1 = q0 + 8 * 64;
        #pragma unroll
        for (int ks = 0; ks < 4; ks++) {
            float2 x0 = *(const float2*)(q0 + 16 * ks);
            float2 x1 = *(const float2*)(q1 + 16 * ks);
            float2 x2 = *(const float2*)(q0 + 16 * ks + 8);
            float2 x3 = *(const float2*)(q1 + 16 * ks + 8);
            qfr[ks][0] = pkh(x0.x * QSCALE, x0.y * QSCALE);
            qfr[ks][1] = pkh(x1.x * QSCALE, x1.y * QSCALE);
            qfr[ks][2] = pkh(x2.x * QSCALE, x2.y * QSCALE);
            qfr[ks][3] = pkh(x3.x * QSCALE, x3.y * QSCALE);
        }
    }

    float oacc[8][4];
    #pragma unroll
    for (int i = 0; i < 8; i++)
        #pragma unroll
        for (int c = 0; c < 4; c++) oacc[i][c] = 0.f;
    float lacc[4] = {0.f, 0.f, 0.f, 0.f};   // row-sum accumulator (ones-MMA)

    // tile 0 must be complete (it may be the only pending group, or the older of two)
    if (nkt >= 1) CPWAIT1(); else CPWAIT0();
    __syncthreads();

    uint32_t bufo = 0;   // stage byte-offset of current tile (ring of 3)

    for (int it = 0; it <= nkt; it++) {
        const int kt = kt0 + it;
        const int kbase = kt * 64;
        const uint32_t kaddr = sb + bufo;
        const uint32_t vaddr = kaddr + OVH;

        // issue copies for tile it+2 into the +2 ring slot
        const bool issued = (it + 2 <= nkt);
        if (issued) {
            uint32_t nb = bufo + 2 * BUFSZ;
            if (nb >= 3 * BUFSZ) nb -= 3 * BUFSZ;
            issue_tile(sb + nb, gK + ((size_t)(kt + 2) << 13), gV + ((size_t)(kt + 2) << 13), tid);
            CPCOMMIT();
        }

        const int rk = r0 - kbase;
        const bool fullvalid = (rk >= 63) && ((unsigned)(rk + 15) <= uw);

        if (fullvalid) {
            // ================= interior fast path: zero masks, zero range checks ==========
            float sacc[8][4];
            #pragma unroll
            for (int i = 0; i < 8; i++)
                #pragma unroll
                for (int cc = 0; cc < 4; cc++) sacc[i][cc] = -EBIAS;

            #pragma unroll
            for (int ks = 0; ks < 4; ks++) {
                const uint32_t kb = kaddr + swK[ks];
                #pragma unroll
                for (int np = 0; np < 8; np += 2) {
                    uint32_t kh4[4];
                    ldsm4(kb + (uint32_t)(np * 1024), kh4);
                    mma_f16(sacc[np],     qfr[ks], kh4[0], kh4[1]);
                    mma_f16(sacc[np + 1], qfr[ks], kh4[2], kh4[3]);
                }
            }

            uint32_t pA[8], pB[8];
            #pragma unroll
            for (int nt = 0; nt < 8; nt++) {
                pA[nt] = pkh(ex2f(sacc[nt][0]), ex2f(sacc[nt][1]));
                pB[nt] = pkh(ex2f(sacc[nt][2]), ex2f(sacc[nt][3]));
            }

            #pragma unroll
            for (int ks = 0; ks < 4; ks++) {
                uint32_t ph[4];
                ph[0] = pA[2 * ks];     ph[1] = pB[2 * ks];
                ph[2] = pA[2 * ks + 1]; ph[3] = pB[2 * ks + 1];
                mma_f16(lacc, ph, HONES, HONES);
                const uint32_t vks = vaddr + (uint32_t)(ks * 2048);
                #pragma unroll
                for (int dp = 0; dp < 4; dp++) {
                    uint32_t vh4[4];
                    ldsm4t(vks + swV[dp], vh4);
                    mma_f16(oacc[2 * dp],     ph, vh4[0], vh4[1]);
                    mma_f16(oacc[2 * dp + 1], ph, vh4[2], vh4[3]);
                }
            }
        } else {
            // ================= boundary path (masked body) ================================
            int jlo, jhi;
            {
                int d = r0 - (int)uw - kbase;
                jlo = d > 0 ? (d >> 3) : 0;
                int e = r0 + 15 - kbase;
                jhi = e >= 0 ? ((e >> 3) + 1) : 0;
                if (jhi > 8) jhi = 8;
                if (jlo > jhi) jlo = jhi;
            }

            float sacc[8][4];
            #pragma unroll
            for (int i = 0; i < 8; i++)
                #pragma unroll
                for (int cc = 0; cc < 4; cc++) sacc[i][cc] = -EBIAS;

            #pragma unroll
            for (int ks = 0; ks < 4; ks++) {
                const uint32_t kb = kaddr + swK[ks];
                #pragma unroll
                for (int np = 0; np < 8; np += 2) {
                    if (np + 2 <= jlo || np >= jhi) continue;
                    uint32_t kh4[4];
                    ldsm4(kb + (uint32_t)(np * 1024), kh4);
                    mma_f16(sacc[np],     qfr[ks], kh4[0], kh4[1]);
                    mma_f16(sacc[np + 1], qfr[ks], kh4[2], kh4[3]);
                }
            }

            uint32_t pA[8], pB[8];
            const int d0 = rq0 - kbase - 2 * t4;
            #pragma unroll
            for (int nt = 0; nt < 8; nt++) {
                if (nt >= jlo && nt < jhi) {
                    const int diff = d0 - 8 * nt;
                    float p0 = ((unsigned)(diff)     <= uw) ? ex2f(sacc[nt][0]) : 0.f;
                    float p1 = ((unsigned)(diff - 1) <= uw) ? ex2f(sacc[nt][1]) : 0.f;
                    float p2 = ((unsigned)(diff + 8) <= uw) ? ex2f(sacc[nt][2]) : 0.f;
                    float p3 = ((unsigned)(diff + 7) <= uw) ? ex2f(sacc[nt][3]) : 0.f;
                    pA[nt] = pkh(p0, p1);
                    pB[nt] = pkh(p2, p3);
                } else {
                    pA[nt] = 0u; pB[nt] = 0u;
                }
            }

            const int klo2 = jlo >> 1, khi2 = (jhi + 1) >> 1;
            #pragma unroll
            for (int ks = 0; ks < 4; ks++) {
                if (ks < klo2 || ks >= khi2) continue;
                uint32_t ph[4];
                ph[0] = pA[2 * ks];     ph[1] = pB[2 * ks];
                ph[2] = pA[2 * ks + 1]; ph[3] = pB[2 * ks + 1];
                mma_f16(lacc, ph, HONES, HONES);
                const uint32_t vks = vaddr + (uint32_t)(ks * 2048);
                #pragma unroll
                for (int dp = 0; dp < 4; dp++) {
                    uint32_t vh4[4];
                    ldsm4t(vks + swV[dp], vh4);
                    mma_f16(oacc[2 * dp],     ph, vh4[0], vh4[1]);
                    mma_f16(oacc[2 * dp + 1], ph, vh4[2], vh4[3]);
                }
            }
        }

        // ensure tile it+1 has landed (its copy is the older pending group)
        if (issued) CPWAIT1();
        else if (it + 1 <= nkt) CPWAIT0();
        __syncthreads();

        bufo += BUFSZ;
        if (bufo == 3 * BUFSZ) bufo = 0;
    }

    if (split) {
        // ---- write unnormalized partial O + l to scratch ----
        float* po = g_po + ((size_t)(pid * 2 + part)) * 8192;
        const int lrow = warp * 16 + g;
        #pragma unroll
        for (int dt = 0; dt < 8; dt++) {
            const int col = dt * 8 + 2 * t4;
            *(float2*)(po + lrow * 64 + col)       = make_float2(oacc[dt][0], oacc[dt][1]);
            *(float2*)(po + (lrow + 8) * 64 + col) = make_float2(oacc[dt][2], oacc[dt][3]);
        }
        if (t4 == 0) {
            g_pl[(pid * 2 + part) * 128 + lrow]     = lacc[0];
            g_pl[(pid * 2 + part) * 128 + lrow + 8] = lacc[2];
        }
    } else {
        const float inv0 = 1.0f / lacc[0];   // diagonal key always valid -> l > 0
        const float inv1 = 1.0f / lacc[2];
        float* o0 = Og + (size_t)rq0 * 64;
        float* o1 = Og + (size_t)(rq0 + 8) * 64;
        #pragma unroll
        for (int dt = 0; dt < 8; dt++) {
            const int col = dt * 8 + 2 * t4;
            *(float2*)(o0 + col) = make_float2(oacc[dt][0] * inv0, oacc[dt][1] * inv0);
            *(float2*)(o1 + col) = make_float2(oacc[dt][2] * inv1, oacc[dt][3] * inv1);
        }
    }
}

extern "C" void kernel_launch(void* const* d_in, const int* in_sizes, int n_in,
                              void* d_out, int out_size)
{
    (void)in_sizes; (void)n_in; (void)out_size;
    const float* Q  = (const float*)d_in[0];
    const float* K  = (const float*)d_in[1];
    const float* V  = (const float*)d_in[2];
    const int*   WS = (const int*)d_in[3];
    float* Out = (float*)d_out;

    // pass 1: fp32 -> fp16 K/V tile images in global scratch
    prep_kernel<<<dim3(1024, 2), 256>>>(K, V);

    // pass 2: attention (512 regular + 64 split-B CTAs)
    cudaFuncSetAttribute(dswa_mma_kernel, cudaFuncAttributeMaxDynamicSharedMemorySize, SMTOT);
    dswa_mma_kernel<<<576, 256, SMTOT>>>(Q, WS, Out);

    // pass 3: combine split-K partials
    combine_kernel<<<512, 256>>>(Out);
}

// round 17
// speedup vs baseline: 1.0496x; 1.0496x over previous
#include <cuda_runtime.h>
#include <cuda_fp16.h>
#include <cstdint>

#define TSEQ 2048
#define HEADS 16

// ---- global scratch: fp16 K/V tile images + split-K partials ----
#define REG8MB 8388608
#define SCR_K 0
#define SCR_V REG8MB
__device__ __align__(16) unsigned char g_scratch[2 * REG8MB];
__device__ __align__(16) float g_po[64 * 2 * 128 * 64];   // [pair][part][row][64]
__device__ __align__(16) float g_pl[64 * 2 * 128];        // [pair][part][row]

// smem: 3-stage ring of {K,V} tiles
#define BUFSZ 16384
#define OKH 0
#define OVH 8192
#define SMTOT (3 * BUFSZ)   // 49152

#define SW(o) ((o) ^ (((o) >> 3) & 0x70))

#define QSCALE 0.18033688011112042f    // 0.125 * log2(e)
#define EBIAS  11.541560327111708f     // 8 * log2(e)
#define HONES  0x3C003C00u             // fp16x2 {1.0, 1.0}

__device__ __forceinline__ uint32_t smem_u32(const void* p) {
    uint32_t a;
    asm("{ .reg .u64 t; cvta.to.shared.u64 t, %1; cvt.u32.u64 %0, t; }" : "=r"(a) : "l"(p));
    return a;
}
#define CPA16(sa, g) asm volatile("cp.async.cg.shared.global [%0], [%1], 16;" :: "r"(sa), "l"(g))
#define CPCOMMIT()   asm volatile("cp.async.commit_group;" ::: "memory")
#define CPWAIT0()    asm volatile("cp.async.wait_group 0;" ::: "memory")
#define CPWAIT1()    asm volatile("cp.async.wait_group 1;" ::: "memory")

__device__ __forceinline__ void ldsm4(uint32_t addr, uint32_t r[4]) {
    asm volatile("ldmatrix.sync.aligned.m8n8.x4.shared.b16 {%0,%1,%2,%3}, [%4];"
        : "=r"(r[0]), "=r"(r[1]), "=r"(r[2]), "=r"(r[3]) : "r"(addr));
}
__device__ __forceinline__ void ldsm4t(uint32_t addr, uint32_t r[4]) {
    asm volatile("ldmatrix.sync.aligned.m8n8.x4.trans.shared.b16 {%0,%1,%2,%3}, [%4];"
        : "=r"(r[0]), "=r"(r[1]), "=r"(r[2]), "=r"(r[3]) : "r"(addr));
}
__device__ __forceinline__ void mma_f16(float c[4], const uint32_t a[4], uint32_t b0, uint32_t b1) {
    asm volatile("mma.sync.aligned.m16n8k16.row.col.f32.f16.f16.f32 "
        "{%0,%1,%2,%3}, {%4,%5,%6,%7}, {%8,%9}, {%0,%1,%2,%3};"
        : "+f"(c[0]), "+f"(c[1]), "+f"(c[2]), "+f"(c[3])
        : "r"(a[0]), "r"(a[1]), "r"(a[2]), "r"(a[3]), "r"(b0), "r"(b1));
}
__device__ __forceinline__ uint32_t pkh(float a, float b) {
    __half2 h = __floats2half2_rn(a, b);
    return *(uint32_t*)&h;
}
__device__ __forceinline__ float ex2f(float x) {
    float y; asm("ex2.approx.f32 %0, %1;" : "=f"(y) : "f"(x)); return y;
}

// ---------------- pre-pass: fp32 -> fp16 K/V tile images ----------------
// R15 mapping (8 threads/row, full-line-coalesced stores) but each thread
// handles TWO far-apart groups: 4 independent LDG.128 batched, then 2 STG.128.
#define PREP_HALF 262144   // 16B-groups per half per tensor (total 524288)
__global__ void __launch_bounds__(256)
prep_kernel(const float* __restrict__ K, const float* __restrict__ V)
{
    const int t = blockIdx.x * 256 + threadIdx.x;
    const int which = blockIdx.y;                     // 0=K 1=V
    const float* srcb = (which == 0) ? K : V;
    const size_t base = (which == 0) ? SCR_K : SCR_V;

    const int g0 = t;
    const int g1 = t + PREP_HALF;

    const int bh0 = g0 >> 14, rem0 = g0 & 16383;
    const int row0 = rem0 >> 3, d80 = rem0 & 7;
    const int bh1 = g1 >> 14, rem1 = g1 & 16383;
    const int row1 = rem1 >> 3, d81 = rem1 & 7;

    const float* s0 = srcb + ((size_t)bh0 << 17) + row0 * 64 + d80 * 8;
    const float* s1 = srcb + ((size_t)bh1 << 17) + row1 * 64 + d81 * 8;

    // 4 independent 16B loads (MLP=4)
    float4 a0 = *(const float4*)(s0);
    float4 a1 = *(const float4*)(s0 + 4);
    float4 b0 = *(const float4*)(s1);
    float4 b1 = *(const float4*)(s1 + 4);

    uint4 h0, h1;
    h0.x = pkh(a0.x, a0.y); h0.y = pkh(a0.z, a0.w);
    h0.z = pkh(a1.x, a1.y); h0.w = pkh(a1.z, a1.w);
    h1.x = pkh(b0.x, b0.y); h1.y = pkh(b0.z, b0.w);
    h1.z = pkh(b1.x, b1.y); h1.w = pkh(b1.z, b1.w);

    const uint32_t off0 = ((uint32_t)bh0 << 18) + (uint32_t)((row0 >> 6) << 13)
                        + SW((uint32_t)(((row0 & 63) << 7) + (d80 << 4)));
    const uint32_t off1 = ((uint32_t)bh1 << 18) + (uint32_t)((row1 >> 6) << 13)
                        + SW((uint32_t)(((row1 & 63) << 7) + (d81 << 4)));
    *(uint4*)(g_scratch + base + off0) = h0;   // warp-contiguous: full 128B lines
    *(uint4*)(g_scratch + base + off1) = h1;
}

// ---------------- combine pass for split-K pairs ----------------
__global__ void __launch_bounds__(256)
combine_kernel(float* __restrict__ O)
{
    const int gid = blockIdx.x * 256 + threadIdx.x;   // 131072 float4s
    const int p   = gid >> 11;
    const int rem = gid & 2047;
    const int row = rem >> 4;

    const float4 va = ((const float4*)g_po)[(p * 2 + 0) * 2048 + rem];
    const float4 vb = ((const float4*)g_po)[(p * 2 + 1) * 2048 + rem];
    const float inv = 1.0f / (g_pl[(p * 2 + 0) * 128 + row] + g_pl[(p * 2 + 1) * 128 + row]);
    float4 o = make_float4((va.x + vb.x) * inv, (va.y + vb.y) * inv,
                           (va.z + vb.z) * inv, (va.w + vb.w) * inv);

    const int qt = 8 + (p & 7), h = 12 + ((p >> 3) & 3), b = p >> 5;
    const int bh = b * HEADS + h;
    float* dst = O + (size_t)bh * TSEQ * 64 + (size_t)(qt * 128) * 64 + rem * 4;
    *(float4*)dst = o;
}

// ---------------- main kernel ----------------
__device__ __forceinline__ void issue_tile(uint32_t dst, const unsigned char* gk,
                                           const unsigned char* gv, int tid) {
    const uint32_t o = (uint32_t)tid * 32;
    CPA16(dst + OKH + o,      gk + o);
    CPA16(dst + OKH + o + 16, gk + o + 16);
    CPA16(dst + OVH + o,      gv + o);
    CPA16(dst + OVH + o + 16, gv + o + 16);
}

__global__ void __launch_bounds__(256, 2)
dswa_mma_kernel(const float* __restrict__ Q, const int* __restrict__ WS,
                float* __restrict__ O)
{
    extern __shared__ char sm[];
    const uint32_t sb = smem_u32(sm);
    const int tid  = threadIdx.x;
    const int lane = tid & 31;
    const int warp = tid >> 5;

    // ---- work decode: first 64 CTAs are split part-B halves (longest first) ----
    int b, h, qt, part = 0, pid = 0;
    bool split = false;
    {
        const int idx = blockIdx.x;
        if (idx < 64) {
            pid = idx; part = 1; split = true;
            qt = 8 + (pid & 7); h = 12 + ((pid >> 3) & 3); b = pid >> 5;
        } else {
            const int e = idx - 64;
            qt = 15 - (e & 15); h = 15 - ((e >> 4) & 15); b = e >> 8;
            if (h >= 12 && qt >= 8) {
                split = true; part = 0;
                pid = (b << 5) | ((h - 12) << 3) | (qt - 8);
            }
        }
    }
    const int qbase = qt * 128;
    const int bh = b * HEADS + h;

    const unsigned uw = (unsigned)WS[h];
    float* Og = O + (size_t)bh * TSEQ * 64;

    const size_t bhoff = (size_t)bh << 18;
    const unsigned char* gK = g_scratch + SCR_K + bhoff;
    const unsigned char* gV = g_scratch + SCR_V + bhoff;

    int klo = qbase - (int)uw; if (klo < 0) klo = 0;
    int kt0 = klo >> 6;
    int kt1 = (qbase + 127) >> 6;
    if (split) { if (part == 0) kt1 = qt; else kt0 = qt + 1; }   // full-window: klo=0
    const int nkt = kt1 - kt0;

    // ---- prologue: first two K/V tiles via cp.async (3-stage ring) ----
    issue_tile(sb, gK + ((size_t)kt0 << 13), gV + ((size_t)kt0 << 13), tid);
    CPCOMMIT();
    if (nkt >= 1) {
        issue_tile(sb + BUFSZ, gK + ((size_t)(kt0 + 1) << 13), gV + ((size_t)(kt0 + 1) << 13), tid);
        CPCOMMIT();
    }

    // ---- lane mapping ----
    const int l7 = lane & 7, jm = lane >> 3;
    const uint32_t krowb = (uint32_t)((l7 + ((jm & 2) << 2)) * 128 + ((jm & 1) << 4));
    const uint32_t vrowb = (uint32_t)((l7 + ((jm & 1) << 3)) * 128 + ((jm & 2) << 3));
    uint32_t swK[4], swV[4];
    #pragma unroll
    for (int ks = 0; ks < 4; ks++) {
        swK[ks] = SW(krowb + (uint32_t)(ks * 32));
        swV[ks] = SW(vrowb + (uint32_t)(ks * 32));   // indexed by dp below
    }

    const int g  = lane >> 2;
    const int t4 = lane & 3;
    const int r0  = qbase + warp * 16;
    const int rq0 = r0 + g;

    // ---- Q fragments: direct fp32 global load -> fp16 fragments (once) ----
    uint32_t qfr[4][4];
    {
        const float* q0 = Q + (size_t)bh * TSEQ * 64 + (size_t)(r0 + g) * 64 + 2 * t4;
        const float* q1 = q0 + 8 * 64;
        #pragma unroll
        for (int ks = 0; ks < 4; ks++) {
            float2 x0 = *(const float2*)(q0 + 16 * ks);
            float2 x1 = *(const float2*)(q1 + 16 * ks);
            float2 x2 = *(const float2*)(q0 + 16 * ks + 8);
            float2 x3 = *(const float2*)(q1 + 16 * ks + 8);
            qfr[ks][0] = pkh(x0.x * QSCALE, x0.y * QSCALE);
            qfr[ks][1] = pkh(x1.x * QSCALE, x1.y * QSCALE);
            qfr[ks][2] = pkh(x2.x * QSCALE, x2.y * QSCALE);
            qfr[ks][3] = pkh(x3.x * QSCALE, x3.y * QSCALE);
        }
    }

    float oacc[8][4];
    #pragma unroll
    for (int i = 0; i < 8; i++)
        #pragma unroll
        for (int c = 0; c < 4; c++) oacc[i][c] = 0.f;
    float lacc[4] = {0.f, 0.f, 0.f, 0.f};   // row-sum accumulator (ones-MMA)

    // tile 0 must be complete (it may be the only pending group, or the older of two)
    if (nkt >= 1) CPWAIT1(); else CPWAIT0();
    __syncthreads();

    uint32_t bufo = 0;   // stage byte-offset of current tile (ring of 3)

    for (int it = 0; it <= nkt; it++) {
        const int kt = kt0 + it;
        const int kbase = kt * 64;
        const uint32_t kaddr = sb + bufo;
        const uint32_t vaddr = kaddr + OVH;

        // issue copies for tile it+2 into the +2 ring slot
        const bool issued = (it + 2 <= nkt);
        if (issued) {
            uint32_t nb = bufo + 2 * BUFSZ;
            if (nb >= 3 * BUFSZ) nb -= 3 * BUFSZ;
            issue_tile(sb + nb, gK + ((size_t)(kt + 2) << 13), gV + ((size_t)(kt + 2) << 13), tid);
            CPCOMMIT();
        }

        const int rk = r0 - kbase;
        const bool fullvalid = (rk >= 63) && ((unsigned)(rk + 15) <= uw);

        if (fullvalid) {
            // ================= interior fast path: zero masks, zero range checks ==========
            float sacc[8][4];
            #pragma unroll
            for (int i = 0; i < 8; i++)
                #pragma unroll
                for (int cc = 0; cc < 4; cc++) sacc[i][cc] = -EBIAS;

            #pragma unroll
            for (int ks = 0; ks < 4; ks++) {
                const uint32_t kb = kaddr + swK[ks];
                #pragma unroll
                for (int np = 0; np < 8; np += 2) {
                    uint32_t kh4[4];
                    ldsm4(kb + (uint32_t)(np * 1024), kh4);
                    mma_f16(sacc[np],     qfr[ks], kh4[0], kh4[1]);
                    mma_f16(sacc[np + 1], qfr[ks], kh4[2], kh4[3]);
                }
            }

            uint32_t pA[8], pB[8];
            #pragma unroll
            for (int nt = 0; nt < 8; nt++) {
                pA[nt] = pkh(ex2f(sacc[nt][0]), ex2f(sacc[nt][1]));
                pB[nt] = pkh(ex2f(sacc[nt][2]), ex2f(sacc[nt][3]));
            }

            #pragma unroll
            for (int ks = 0; ks < 4; ks++) {
                uint32_t ph[4];
                ph[0] = pA[2 * ks];     ph[1] = pB[2 * ks];
                ph[2] = pA[2 * ks + 1]; ph[3] = pB[2 * ks + 1];
                mma_f16(lacc, ph, HONES, HONES);
                const uint32_t vks = vaddr + (uint32_t)(ks * 2048);
                #pragma unroll
                for (int dp = 0; dp < 4; dp++) {
                    uint32_t vh4[4];
                    ldsm4t(vks + swV[dp], vh4);
                    mma_f16(oacc[2 * dp],     ph, vh4[0], vh4[1]);
                    mma_f16(oacc[2 * dp + 1], ph, vh4[2], vh4[3]);
                }
            }
        } else {
            // ================= boundary path (masked body) ================================
            int jlo, jhi;
            {
                int d = r0 - (int)uw - kbase;
                jlo = d > 0 ? (d >> 3) : 0;
                int e = r0 + 15 - kbase;
                jhi = e >= 0 ? ((e >> 3) + 1) : 0;
                if (jhi > 8) jhi = 8;
                if (jlo > jhi) jlo = jhi;
            }

            float sacc[8][4];
            #pragma unroll
            for (int i = 0; i < 8; i++)
                #pragma unroll
                for (int cc = 0; cc < 4; cc++) sacc[i][cc] = -EBIAS;

            #pragma unroll
            for (int ks = 0; ks < 4; ks++) {
                const uint32_t kb = kaddr + swK[ks];
                #pragma unroll
                for (int np = 0; np < 8; np += 2) {
                    if (np + 2 <= jlo || np >= jhi) continue;
                    uint32_t kh4[4];
                    ldsm4(kb + (uint32_t)(np * 1024), kh4);
                    mma_f16(sacc[np],     qfr[ks], kh4[0], kh4[1]);
                    mma_f16(sacc[np + 1], qfr[ks], kh4[2], kh4[3]);
                }
            }

            uint32_t pA[8], pB[8];
            const int d0 = rq0 - kbase - 2 * t4;
            #pragma unroll
            for (int nt = 0; nt < 8; nt++) {
                if (nt >= jlo && nt < jhi) {
                    const int diff = d0 - 8 * nt;
                    float p0 = ((unsigned)(diff)     <= uw) ? ex2f(sacc[nt][0]) : 0.f;
                    float p1 = ((unsigned)(diff - 1) <= uw) ? ex2f(sacc[nt][1]) : 0.f;
                    float p2 = ((unsigned)(diff + 8) <= uw) ? ex2f(sacc[nt][2]) : 0.f;
                    float p3 = ((unsigned)(diff + 7) <= uw) ? ex2f(sacc[nt][3]) : 0.f;
                    pA[nt] = pkh(p0, p1);
                    pB[nt] = pkh(p2, p3);
                } else {
                    pA[nt] = 0u; pB[nt] = 0u;
                }
            }

            const int klo2 = jlo >> 1, khi2 = (jhi + 1) >> 1;
            #pragma unroll
            for (int ks = 0; ks < 4; ks++) {
                if (ks < klo2 || ks >= khi2) continue;
                uint32_t ph[4];
                ph[0] = pA[2 * ks];     ph[1] = pB[2 * ks];
                ph[2] = pA[2 * ks + 1]; ph[3] = pB[2 * ks + 1];
                mma_f16(lacc, ph, HONES, HONES);
                const uint32_t vks = vaddr + (uint32_t)(ks * 2048);
                #pragma unroll
                for (int dp = 0; dp < 4; dp++) {
                    uint32_t vh4[4];
                    ldsm4t(vks + swV[dp], vh4);
                    mma_f16(oacc[2 * dp],     ph, vh4[0], vh4[1]);
                    mma_f16(oacc[2 * dp + 1], ph, vh4[2], vh4[3]);
                }
            }
        }

        // ensure tile it+1 has landed (its copy is the older pending group)
        if (issued) CPWAIT1();
        else if (it + 1 <= nkt) CPWAIT0();
        __syncthreads();

        bufo += BUFSZ;
        if (bufo == 3 * BUFSZ) bufo = 0;
    }

    if (split) {
        // ---- write unnormalized partial O + l to scratch ----
        float* po = g_po + ((size_t)(pid * 2 + part)) * 8192;
        const int lrow = warp * 16 + g;
        #pragma unroll
        for (int dt = 0; dt < 8; dt++) {
            const int col = dt * 8 + 2 * t4;
            *(float2*)(po + lrow * 64 + col)       = make_float2(oacc[dt][0], oacc[dt][1]);
            *(float2*)(po + (lrow + 8) * 64 + col) = make_float2(oacc[dt][2], oacc[dt][3]);
        }
        if (t4 == 0) {
            g_pl[(pid * 2 + part) * 128 + lrow]     = lacc[0];
            g_pl[(pid * 2 + part) * 128 + lrow + 8] = lacc[2];
        }
    } else {
        const float inv0 = 1.0f / lacc[0];   // diagonal key always valid -> l > 0
        const float inv1 = 1.0f / lacc[2];
        float* o0 = Og + (size_t)rq0 * 64;
        float* o1 = Og + (size_t)(rq0 + 8) * 64;
        #pragma unroll
        for (int dt = 0; dt < 8; dt++) {
            const int col = dt * 8 + 2 * t4;
            *(float2*)(o0 + col) = make_float2(oacc[dt][0] * inv0, oacc[dt][1] * inv0);
            *(float2*)(o1 + col) = make_float2(oacc[dt][2] * inv1, oacc[dt][3] * inv1);
        }
    }
}

extern "C" void kernel_launch(void* const* d_in, const int* in_sizes, int n_in,
                              void* d_out, int out_size)
{
    (void)in_sizes; (void)n_in; (void)out_size;
    const float* Q  = (const float*)d_in[0];
    const float* K  = (const float*)d_in[1];
    const float* V  = (const float*)d_in[2];
    const int*   WS = (const int*)d_in[3];
    float* Out = (float*)d_out;

    // pass 1: fp32 -> fp16 K/V tile images in global scratch
    prep_kernel<<<dim3(1024, 2), 256>>>(K, V);

    // pass 2: attention (512 regular + 64 split-B CTAs)
    cudaFuncSetAttribute(dswa_mma_kernel, cudaFuncAttributeMaxDynamicSharedMemorySize, SMTOT);
    dswa_mma_kernel<<<576, 256, SMTOT>>>(Q, WS, Out);

    // pass 3: combine split-K partials
    combine_kernel<<<512, 256>>>(Out);
}